// round 13
// baseline (speedup 1.0000x reference)
#include <cuda_runtime.h>
#include <cuda_bf16.h>
#include <cstdint>

#define NN   100000
#define FIN  128
#define HH   64
#define GG   512
#define CAP  64

__device__ __align__(16) float g_dinv[NN];
__device__ __align__(16) __nv_bfloat16 g_xs[NN * HH];
__device__ __align__(16) __nv_bfloat16 g_h1[NN * HH];
__device__ __align__(16) float g_pool[GG * HH];
__device__ __align__(16) float g_cnt[GG];
__device__            int   g_deg[NN];
__device__ __align__(16) int g_bucket[NN * CAP];

// Side stream + fork/join events, created once at load (no device memory).
static cudaStream_t g_s1;
static cudaEvent_t  g_ev_fork, g_ev_join;
namespace {
struct _StreamInit {
    _StreamInit() {
        cudaStreamCreateWithFlags(&g_s1, cudaStreamNonBlocking);
        cudaEventCreateWithFlags(&g_ev_fork, cudaEventDisableTiming);
        cudaEventCreateWithFlags(&g_ev_join, cudaEventDisableTiming);
    }
};
_StreamInit _g_stream_init;
}

// ---------------------------------------------------------------------------
__global__ void init_kernel(int* __restrict__ deg, float* __restrict__ pool,
                            float* __restrict__ cnt, int n) {
    int i = blockIdx.x * blockDim.x + threadIdx.x;
    if (i < n) deg[i] = 0;
    if (i < GG * HH) pool[i] = 0.f;
    if (i < GG) cnt[i] = 0.f;
}

__global__ void fill_kernel(const int* __restrict__ src, const int* __restrict__ dst,
                            int* __restrict__ cur, int* __restrict__ bucket, int E) {
    int base = (blockIdx.x * blockDim.x + threadIdx.x) * 4;
    #pragma unroll
    for (int j = 0; j < 4; j++) {
        int i = base + j;
        if (i < E) {
            int d = __ldg(&dst[i]);
            int s = __ldg(&src[i]);
            int pos = atomicAdd(&cur[d], 1);
            if (pos < CAP) bucket[d * CAP + pos] = s;
        }
    }
}

__global__ void dinv_kernel(const int* __restrict__ deg, float* __restrict__ dinv, int n) {
    int i = blockIdx.x * blockDim.x + threadIdx.x;
    if (i < n) dinv[i] = rsqrtf((float)deg[i] + 1.0f);
}

// xs[node,:] *= dinv[node], f32 math, uint4 granularity (8 bf16 per thread).
__global__ void scale_kernel(__nv_bfloat16* __restrict__ xs,
                             const float* __restrict__ dinv, int n) {
    int i = blockIdx.x * blockDim.x + threadIdx.x;   // uint4 index
    if (i >= n * 8) return;
    float d = __ldg(&dinv[i >> 3]);
    uint4 v = ((const uint4*)xs)[i];
    __nv_bfloat162* pv = (__nv_bfloat162*)&v;
    #pragma unroll
    for (int k = 0; k < 4; k++) {
        float2 f = __bfloat1622float2(pv[k]);
        pv[k] = __float22bfloat162_rn(make_float2(f.x * d, f.y * d));
    }
    ((uint4*)xs)[i] = v;
}

// ---------------------------------------------------------------------------
#define WS_STRIDE 72   // ≡8 mod 32: B-frag conflict-free
#define AS_STRIDE 20   // ≡4 mod 32: A-frag conflict-free (chunk 16)
#define AS2_STRIDE 68  // ≡4 mod 32: A-frag conflict-free (full K=64)

__device__ __forceinline__ uint32_t f2tf32(float f) {
    uint32_t r;
    asm("cvt.rna.tf32.f32 %0, %1;" : "=r"(r) : "f"(f));
    return r;
}
__device__ __forceinline__ uint32_t smem_u32(const void* p) {
    return (uint32_t)__cvta_generic_to_shared(p);
}

#define MMA_TF32(acc, a, b0, b1)                                             \
    asm volatile(                                                            \
        "mma.sync.aligned.m16n8k8.row.col.f32.tf32.tf32.f32 "                \
        "{%0,%1,%2,%3}, {%4,%5,%6,%7}, {%8,%9}, {%0,%1,%2,%3};"              \
        : "+f"(acc[0]), "+f"(acc[1]), "+f"(acc[2]), "+f"(acc[3])             \
        : "r"(a[0]), "r"(a[1]), "r"(a[2]), "r"(a[3]), "r"(b0), "r"(b1))

// ---------------------------------------------------------------------------
// GEMM1: fp32 X[n,128] @ W[128,64] -> bf16 out, UNSCALED.
// M-tile 256/CTA, 8 warps x 32 rows (2 m-tiles/warp) -> B-frags amortized 2x.
// 3-stage cp.async.cg pipeline (L1-bypass for streamed X).
__global__ __launch_bounds__(256) void gemm_f32_kernel(
        const float* __restrict__ X, const float* __restrict__ W,
        __nv_bfloat16* __restrict__ out, int n) {
    const int K = FIN, NC = FIN / 16;
    extern __shared__ uint32_t sm[];
    uint32_t* Ws = sm;                       // 128 * 72
    uint32_t* As = sm + K * WS_STRIDE;       // 3 * 256 * 20

    const int tid  = threadIdx.x;
    const int row0 = blockIdx.x * 256;
    const int warp = tid >> 5;
    const int lane = tid & 31;
    const int r    = lane >> 2;
    const int cq   = lane & 3;
    const int mrow = warp * 32;

    const uint32_t As_base = smem_u32(As);
    auto stage = [&](int c) {
        uint32_t base = As_base + (c % 3) * (256 * AS_STRIDE * 4);
        #pragma unroll
        for (int j = 0; j < 4; j++) {
            int i   = tid + j * 256;       // 0..1023
            int row = i >> 2, seg = i & 3;
            int grow = row0 + row;
            int ok = (grow < n);
            const float* p = X + (long)(ok ? grow : 0) * K + c * 16 + seg * 4;
            uint32_t daddr = base + (uint32_t)(row * AS_STRIDE + seg * 4) * 4;
            int sz = ok ? 16 : 0;
            asm volatile("cp.async.cg.shared.global [%0], [%1], 16, %2;"
                         :: "r"(daddr), "l"(p), "r"(sz));
        }
    };

    stage(0); asm volatile("cp.async.commit_group;");
    stage(1); asm volatile("cp.async.commit_group;");
    stage(2); asm volatile("cp.async.commit_group;");

    // stage W while loads fly
    for (int i4 = tid; i4 < K * 16; i4 += 256) {
        float4 w = __ldg((const float4*)W + i4);
        int flat = i4 * 4;
        uint32_t* d = &Ws[(flat >> 6) * WS_STRIDE + (flat & 63)];
        d[0] = f2tf32(w.x); d[1] = f2tf32(w.y); d[2] = f2tf32(w.z); d[3] = f2tf32(w.w);
    }

    float acc[2][8][4];
    #pragma unroll
    for (int mt = 0; mt < 2; mt++)
        #pragma unroll
        for (int nb = 0; nb < 8; nb++)
            #pragma unroll
            for (int c = 0; c < 4; c++) acc[mt][nb][c] = 0.f;

    #pragma unroll
    for (int c = 0; c < NC; c++) {
        if (c + 2 < NC)      asm volatile("cp.async.wait_group 2;");
        else if (c + 1 < NC) asm volatile("cp.async.wait_group 1;");
        else                 asm volatile("cp.async.wait_group 0;");
        __syncthreads();

        const uint32_t* A = As + (c % 3) * (256 * AS_STRIDE);
        #pragma unroll
        for (int ks = 0; ks < 2; ks++) {
            int kl = ks * 8;
            uint32_t a[2][4];
            #pragma unroll
            for (int mt = 0; mt < 2; mt++) {
                int rr = mrow + mt * 16;
                a[mt][0] = A[(rr + r)     * AS_STRIDE + kl + cq];
                a[mt][1] = A[(rr + r + 8) * AS_STRIDE + kl + cq];
                a[mt][2] = A[(rr + r)     * AS_STRIDE + kl + cq + 4];
                a[mt][3] = A[(rr + r + 8) * AS_STRIDE + kl + cq + 4];
            }
            #pragma unroll
            for (int nb = 0; nb < 8; nb++) {
                uint32_t b0 = Ws[(c * 16 + kl + cq)     * WS_STRIDE + nb * 8 + r];
                uint32_t b1 = Ws[(c * 16 + kl + cq + 4) * WS_STRIDE + nb * 8 + r];
                MMA_TF32(acc[0][nb], a[0], b0, b1);
                MMA_TF32(acc[1][nb], a[1], b0, b1);
            }
        }
        __syncthreads();
        if (c + 3 < NC) { stage(c + 3); asm volatile("cp.async.commit_group;"); }
    }

    #pragma unroll
    for (int mt = 0; mt < 2; mt++) {
        int row_a = row0 + mrow + mt * 16 + r;
        int row_b = row_a + 8;
        #pragma unroll
        for (int nb = 0; nb < 8; nb++) {
            int col = nb * 8 + cq * 2;
            if (row_a < n) {
                __nv_bfloat162 v = __float22bfloat162_rn(
                    make_float2(acc[mt][nb][0], acc[mt][nb][1]));
                *(__nv_bfloat162*)&out[(long)row_a * HH + col] = v;
            }
            if (row_b < n) {
                __nv_bfloat162 v = __float22bfloat162_rn(
                    make_float2(acc[mt][nb][2], acc[mt][nb][3]));
                *(__nv_bfloat162*)&out[(long)row_b * HH + col] = v;
            }
        }
    }
}

// ---------------------------------------------------------------------------
// GEMM2: bf16 X[n,64] @ W[64,64] -> bf16 out, scaled by dinv[row]. 256 threads.
__global__ __launch_bounds__(256) void gemm_bf16_kernel(
        const __nv_bfloat16* __restrict__ X, const float* __restrict__ W,
        const float* __restrict__ dinv, __nv_bfloat16* __restrict__ out, int n) {
    extern __shared__ uint32_t sm[];
    uint32_t* Ws = sm;                         // 64 * 72
    uint32_t* As = sm + 64 * WS_STRIDE;        // 128 * 68

    const int tid  = threadIdx.x;
    const int row0 = blockIdx.x * 128;
    const int warp = tid >> 5;
    const int lane = tid & 31;
    const int r    = lane >> 2;
    const int cq   = lane & 3;
    const int mrow = warp * 16;

    for (int i4 = tid; i4 < 64 * 16; i4 += 256) {
        float4 w = __ldg((const float4*)W + i4);
        int flat = i4 * 4;
        uint32_t* d = &Ws[(flat >> 6) * WS_STRIDE + (flat & 63)];
        d[0] = f2tf32(w.x); d[1] = f2tf32(w.y); d[2] = f2tf32(w.z); d[3] = f2tf32(w.w);
    }

    #pragma unroll
    for (int j = 0; j < 4; j++) {
        int i   = tid + j * 256;       // 0..1023
        int row = i >> 3, seg = i & 7;
        int grow = row0 + row;
        uint4 v = (grow < n) ? __ldg((const uint4*)(X + (long)grow * HH) + seg)
                             : make_uint4(0, 0, 0, 0);
        uint32_t* d = &As[row * AS2_STRIDE + seg * 8];
        d[0] = v.x << 16; d[1] = v.x & 0xFFFF0000u;
        d[2] = v.y << 16; d[3] = v.y & 0xFFFF0000u;
        d[4] = v.z << 16; d[5] = v.z & 0xFFFF0000u;
        d[6] = v.w << 16; d[7] = v.w & 0xFFFF0000u;
    }
    __syncthreads();

    float acc[8][4];
    #pragma unroll
    for (int nb = 0; nb < 8; nb++)
        #pragma unroll
        for (int c = 0; c < 4; c++) acc[nb][c] = 0.f;

    #pragma unroll
    for (int kg = 0; kg < 8; kg++) {
        int kl = kg * 8;
        uint32_t a[4];
        a[0] = As[(mrow + r)     * AS2_STRIDE + kl + cq];
        a[1] = As[(mrow + r + 8) * AS2_STRIDE + kl + cq];
        a[2] = As[(mrow + r)     * AS2_STRIDE + kl + cq + 4];
        a[3] = As[(mrow + r + 8) * AS2_STRIDE + kl + cq + 4];
        #pragma unroll
        for (int nb = 0; nb < 8; nb++) {
            uint32_t b0 = Ws[(kl + cq)     * WS_STRIDE + nb * 8 + r];
            uint32_t b1 = Ws[(kl + cq + 4) * WS_STRIDE + nb * 8 + r];
            MMA_TF32(acc[nb], a, b0, b1);
        }
    }

    int row_a = row0 + mrow + r;
    int row_b = row_a + 8;
    float sa = (row_a < n) ? dinv[row_a] : 0.f;
    float sb = (row_b < n) ? dinv[row_b] : 0.f;
    #pragma unroll
    for (int nb = 0; nb < 8; nb++) {
        int col = nb * 8 + cq * 2;
        if (row_a < n) {
            __nv_bfloat162 v = __float22bfloat162_rn(
                make_float2(acc[nb][0] * sa, acc[nb][1] * sa));
            *(__nv_bfloat162*)&out[(long)row_a * HH + col] = v;
        }
        if (row_b < n) {
            __nv_bfloat162 v = __float22bfloat162_rn(
                make_float2(acc[nb][2] * sb, acc[nb][3] * sb));
            *(__nv_bfloat162*)&out[(long)row_b * HH + col] = v;
        }
    }
}

// ---------------------------------------------------------------------------
// Gather with bf16x2 HADD2 accumulation, 8-edge unroll for MLP.
// xs pre-scaled by dinv[src]. h[n] = relu(dinv[n] * Σ xs[s] + b).
// 8 threads/node, uint4 lanes.
__device__ __forceinline__ void hacc4(__nv_bfloat162* acc, uint4 v) {
    __nv_bfloat162* p = (__nv_bfloat162*)&v;
    acc[0] = __hadd2(acc[0], p[0]);
    acc[1] = __hadd2(acc[1], p[1]);
    acc[2] = __hadd2(acc[2], p[2]);
    acc[3] = __hadd2(acc[3], p[3]);
}

template <bool POOL>
__global__ void gather_kernel(const int* __restrict__ deg, const int* __restrict__ bucket,
                              const __nv_bfloat16* __restrict__ xs,
                              const float* __restrict__ dinv,
                              const float* __restrict__ b,
                              __nv_bfloat16* __restrict__ out,
                              const int* __restrict__ batch,
                              float* __restrict__ pool, float* __restrict__ cntg,
                              int n) {
    int t = blockIdx.x * blockDim.x + threadIdx.x;
    int node = t >> 3;
    if (node >= n) return;
    int lane8 = t & 7;
    int c = lane8 << 3;

    int dcount = __ldg(&deg[node]);
    if (dcount > CAP) dcount = CAP;
    const int* lst = bucket + node * CAP;

    // self-loop message initializes the accumulator
    uint4 sv = __ldg((const uint4*)xs + (long)node * 8 + lane8);
    __nv_bfloat162 acc[4];
    {
        __nv_bfloat162* p = (__nv_bfloat162*)&sv;
        acc[0] = p[0]; acc[1] = p[1]; acc[2] = p[2]; acc[3] = p[3];
    }

    int e = 0;
    for (; e + 8 <= dcount; e += 8) {
        int4 sA = __ldg((const int4*)(lst + e));
        int4 sB = __ldg((const int4*)(lst + e + 4));
        uint4 v0 = __ldg((const uint4*)xs + (long)sA.x * 8 + lane8);
        uint4 v1 = __ldg((const uint4*)xs + (long)sA.y * 8 + lane8);
        uint4 v2 = __ldg((const uint4*)xs + (long)sA.z * 8 + lane8);
        uint4 v3 = __ldg((const uint4*)xs + (long)sA.w * 8 + lane8);
        uint4 v4 = __ldg((const uint4*)xs + (long)sB.x * 8 + lane8);
        uint4 v5 = __ldg((const uint4*)xs + (long)sB.y * 8 + lane8);
        uint4 v6 = __ldg((const uint4*)xs + (long)sB.z * 8 + lane8);
        uint4 v7 = __ldg((const uint4*)xs + (long)sB.w * 8 + lane8);
        hacc4(acc, v0); hacc4(acc, v1); hacc4(acc, v2); hacc4(acc, v3);
        hacc4(acc, v4); hacc4(acc, v5); hacc4(acc, v6); hacc4(acc, v7);
    }
    for (; e + 4 <= dcount; e += 4) {
        int4 sA = __ldg((const int4*)(lst + e));
        uint4 v0 = __ldg((const uint4*)xs + (long)sA.x * 8 + lane8);
        uint4 v1 = __ldg((const uint4*)xs + (long)sA.y * 8 + lane8);
        uint4 v2 = __ldg((const uint4*)xs + (long)sA.z * 8 + lane8);
        uint4 v3 = __ldg((const uint4*)xs + (long)sA.w * 8 + lane8);
        hacc4(acc, v0); hacc4(acc, v1); hacc4(acc, v2); hacc4(acc, v3);
    }
    for (; e < dcount; e++) {
        int s = __ldg(&lst[e]);
        hacc4(acc, __ldg((const uint4*)xs + (long)s * 8 + lane8));
    }

    float sc = __ldg(&dinv[node]);
    float o[8];
    #pragma unroll
    for (int k = 0; k < 4; k++) {
        float2 f = __bfloat1622float2(acc[k]);
        o[k * 2 + 0] = fmaxf(fmaf(sc, f.x, __ldg(&b[c + k * 2 + 0])), 0.f);
        o[k * 2 + 1] = fmaxf(fmaf(sc, f.y, __ldg(&b[c + k * 2 + 1])), 0.f);
    }

    if (!POOL) {
        uint4 pk;
        __nv_bfloat162 h0 = __float22bfloat162_rn(make_float2(o[0], o[1]));
        __nv_bfloat162 h1 = __float22bfloat162_rn(make_float2(o[2], o[3]));
        __nv_bfloat162 h2 = __float22bfloat162_rn(make_float2(o[4], o[5]));
        __nv_bfloat162 h3 = __float22bfloat162_rn(make_float2(o[6], o[7]));
        pk.x = *(uint32_t*)&h0; pk.y = *(uint32_t*)&h1;
        pk.z = *(uint32_t*)&h2; pk.w = *(uint32_t*)&h3;
        *((uint4*)out + (long)node * 8 + lane8) = pk;
    } else {
        int g = __ldg(&batch[node]);
        float* p = pool + g * HH + c;
        asm volatile("red.global.add.v4.f32 [%0], {%1,%2,%3,%4};"
                     :: "l"(p), "f"(o[0]), "f"(o[1]), "f"(o[2]), "f"(o[3]) : "memory");
        asm volatile("red.global.add.v4.f32 [%0], {%1,%2,%3,%4};"
                     :: "l"(p + 4), "f"(o[4]), "f"(o[5]), "f"(o[6]), "f"(o[7]) : "memory");
        if (lane8 == 0) atomicAdd(&cntg[g], 1.0f);
    }
}

// ---------------------------------------------------------------------------
__global__ void head_kernel(const float* __restrict__ pool, const float* __restrict__ cnt,
                            const float* __restrict__ Wl, const float* __restrict__ bl,
                            float* __restrict__ out) {
    int g = blockIdx.x * blockDim.x + threadIdx.x;
    if (g >= GG) return;
    float inv = 1.0f / fmaxf(cnt[g], 1.0f);
    float acc = 0.f;
    #pragma unroll
    for (int k = 0; k < HH; k++) acc += pool[g * HH + k] * __ldg(&Wl[k]);
    float z = acc * inv + __ldg(&bl[0]);
    out[g] = 1.0f / (1.0f + expf(-z));
}

// ---------------------------------------------------------------------------
extern "C" void kernel_launch(void* const* d_in, const int* in_sizes, int n_in,
                              void* d_out, int out_size) {
    const float* x     = (const float*)d_in[0];
    const int*   ei    = (const int*)  d_in[1];
    const int*   batch = (const int*)  d_in[2];
    const float* W1    = (const float*)d_in[3];
    const float* b1    = (const float*)d_in[4];
    const float* W2    = (const float*)d_in[5];
    const float* b2    = (const float*)d_in[6];
    const float* Wl    = (const float*)d_in[7];
    const float* bl    = (const float*)d_in[8];

    const int n = in_sizes[0] / FIN;
    const int E = in_sizes[1] / 2;
    const int* src = ei;
    const int* dst = ei + E;

    float *dinv, *pool, *cnt;
    __nv_bfloat16 *XS, *H1;
    int *deg, *bucket;
    cudaGetSymbolAddress((void**)&dinv,   g_dinv);
    cudaGetSymbolAddress((void**)&XS,     g_xs);
    cudaGetSymbolAddress((void**)&H1,     g_h1);
    cudaGetSymbolAddress((void**)&pool,   g_pool);
    cudaGetSymbolAddress((void**)&cnt,    g_cnt);
    cudaGetSymbolAddress((void**)&deg,    g_deg);
    cudaGetSymbolAddress((void**)&bucket, g_bucket);

    const int SMEM1 = (FIN * WS_STRIDE + 3 * 256 * AS_STRIDE) * 4;  // 98304
    const int SMEM2 = (HH * WS_STRIDE + 128 * AS2_STRIDE) * 4;      // 53248
    cudaFuncSetAttribute(gemm_f32_kernel,
                         cudaFuncAttributeMaxDynamicSharedMemorySize, SMEM1);
    cudaFuncSetAttribute(gemm_bf16_kernel,
                         cudaFuncAttributeMaxDynamicSharedMemorySize, SMEM2);

    const int GB1 = (n + 255) / 256;
    const int GB2 = (n + 127) / 128;

    // main stream: init (deg/pool/cnt)
    init_kernel<<<(n + 255) / 256, 256>>>(deg, pool, cnt, n);

    // fork: side stream builds adjacency + dinv, main stream runs GEMM1
    cudaEventRecord(g_ev_fork, 0);
    cudaStreamWaitEvent(g_s1, g_ev_fork, 0);

    fill_kernel<<<(E / 4 + 255) / 256, 256, 0, g_s1>>>(src, dst, deg, bucket, E);
    dinv_kernel<<<(n + 255) / 256, 256, 0, g_s1>>>(deg, dinv, n);
    cudaEventRecord(g_ev_join, g_s1);

    gemm_f32_kernel<<<GB1, 256, SMEM1>>>(x, W1, XS, n);   // unscaled xs

    // join, then apply dinv scaling to xs (f32 math)
    cudaStreamWaitEvent(0, g_ev_join, 0);
    scale_kernel<<<(n * 8 + 255) / 256, 256>>>(XS, dinv, n);

    // layer 1 aggregate (pure HADD2)
    gather_kernel<false><<<(n * 8 + 255) / 256, 256>>>(
        deg, bucket, XS, dinv, b1, H1, nullptr, nullptr, nullptr, n);

    // layer 2: xs2 = dinv*(h1@W2); aggregate fused with relu + mean-pool
    gemm_bf16_kernel<<<GB2, 256, SMEM2>>>(H1, W2, dinv, XS, n);
    gather_kernel<true><<<(n * 8 + 255) / 256, 256>>>(
        deg, bucket, XS, dinv, b2, nullptr, batch, pool, cnt, n);

    head_kernel<<<(GG + 255) / 256, 256>>>(pool, cnt, Wl, bl, (float*)d_out);
}

// round 14
// speedup vs baseline: 1.0630x; 1.0630x over previous
#include <cuda_runtime.h>
#include <cuda_bf16.h>
#include <cstdint>

#define NN   100000
#define FIN  128
#define HH   64
#define GG   512
#define CAP  64

__device__ __align__(16) float g_dinv[NN];
__device__ __align__(16) __nv_bfloat16 g_xs[NN * HH];
__device__ __align__(16) __nv_bfloat16 g_h1[NN * HH];
__device__ __align__(16) float g_pool[GG * HH];
__device__ __align__(16) float g_cnt[GG];
__device__            int   g_deg[NN];
__device__ __align__(16) int g_bucket[NN * CAP];

// Side stream + fork/join events, created once at load (no device memory).
static cudaStream_t g_s1;
static cudaEvent_t  g_ev_fork, g_ev_join;
namespace {
struct _StreamInit {
    _StreamInit() {
        cudaStreamCreateWithFlags(&g_s1, cudaStreamNonBlocking);
        cudaEventCreateWithFlags(&g_ev_fork, cudaEventDisableTiming);
        cudaEventCreateWithFlags(&g_ev_join, cudaEventDisableTiming);
    }
};
_StreamInit _g_stream_init;
}

// ---------------------------------------------------------------------------
__global__ void init_kernel(int* __restrict__ deg, float* __restrict__ pool,
                            float* __restrict__ cnt, int n) {
    int i = blockIdx.x * blockDim.x + threadIdx.x;
    if (i < n) deg[i] = 0;
    if (i < GG * HH) pool[i] = 0.f;
    if (i < GG) cnt[i] = 0.f;
}

__global__ void fill_kernel(const int* __restrict__ src, const int* __restrict__ dst,
                            int* __restrict__ cur, int* __restrict__ bucket, int E) {
    int base = (blockIdx.x * blockDim.x + threadIdx.x) * 4;
    #pragma unroll
    for (int j = 0; j < 4; j++) {
        int i = base + j;
        if (i < E) {
            int d = __ldg(&dst[i]);
            int s = __ldg(&src[i]);
            int pos = atomicAdd(&cur[d], 1);
            if (pos < CAP) bucket[d * CAP + pos] = s;
        }
    }
}

__global__ void dinv_kernel(const int* __restrict__ deg, float* __restrict__ dinv, int n) {
    int i = blockIdx.x * blockDim.x + threadIdx.x;
    if (i < n) dinv[i] = rsqrtf((float)deg[i] + 1.0f);
}

// xs[node,:] *= dinv[node], f32 math, uint4 granularity (8 bf16 per thread).
__global__ void scale_kernel(__nv_bfloat16* __restrict__ xs,
                             const float* __restrict__ dinv, int n) {
    int i = blockIdx.x * blockDim.x + threadIdx.x;   // uint4 index
    if (i >= n * 8) return;
    float d = __ldg(&dinv[i >> 3]);
    uint4 v = ((const uint4*)xs)[i];
    __nv_bfloat162* pv = (__nv_bfloat162*)&v;
    #pragma unroll
    for (int k = 0; k < 4; k++) {
        float2 f = __bfloat1622float2(pv[k]);
        pv[k] = __float22bfloat162_rn(make_float2(f.x * d, f.y * d));
    }
    ((uint4*)xs)[i] = v;
}

// ---------------------------------------------------------------------------
#define WS_STRIDE 72   // ≡8 mod 32: B-frag conflict-free
#define AS_STRIDE 20   // ≡4 mod 32: A-frag conflict-free (chunk 16)
#define AS2_STRIDE 68  // ≡4 mod 32: A-frag conflict-free (full K=64)

__device__ __forceinline__ uint32_t f2tf32(float f) {
    uint32_t r;
    asm("cvt.rna.tf32.f32 %0, %1;" : "=r"(r) : "f"(f));
    return r;
}
__device__ __forceinline__ uint32_t smem_u32(const void* p) {
    return (uint32_t)__cvta_generic_to_shared(p);
}

#define MMA_TF32(acc, a, b0, b1)                                             \
    asm volatile(                                                            \
        "mma.sync.aligned.m16n8k8.row.col.f32.tf32.tf32.f32 "                \
        "{%0,%1,%2,%3}, {%4,%5,%6,%7}, {%8,%9}, {%0,%1,%2,%3};"              \
        : "+f"(acc[0]), "+f"(acc[1]), "+f"(acc[2]), "+f"(acc[3])             \
        : "r"(a[0]), "r"(a[1]), "r"(a[2]), "r"(a[3]), "r"(b0), "r"(b1))

// ---------------------------------------------------------------------------
// GEMM1: fp32 X[n,128] @ W[128,64] -> bf16 out, UNSCALED.
// M-tile 256/CTA, 8 warps x 32 rows (2 m-tiles/warp) -> B-frags amortized 2x.
// 3-stage cp.async.cg pipeline (L1-bypass for streamed X).
__global__ __launch_bounds__(256) void gemm_f32_kernel(
        const float* __restrict__ X, const float* __restrict__ W,
        __nv_bfloat16* __restrict__ out, int n) {
    const int K = FIN, NC = FIN / 16;
    extern __shared__ uint32_t sm[];
    uint32_t* Ws = sm;                       // 128 * 72
    uint32_t* As = sm + K * WS_STRIDE;       // 3 * 256 * 20

    const int tid  = threadIdx.x;
    const int row0 = blockIdx.x * 256;
    const int warp = tid >> 5;
    const int lane = tid & 31;
    const int r    = lane >> 2;
    const int cq   = lane & 3;
    const int mrow = warp * 32;

    const uint32_t As_base = smem_u32(As);
    auto stage = [&](int c) {
        uint32_t base = As_base + (c % 3) * (256 * AS_STRIDE * 4);
        #pragma unroll
        for (int j = 0; j < 4; j++) {
            int i   = tid + j * 256;       // 0..1023
            int row = i >> 2, seg = i & 3;
            int grow = row0 + row;
            int ok = (grow < n);
            const float* p = X + (long)(ok ? grow : 0) * K + c * 16 + seg * 4;
            uint32_t daddr = base + (uint32_t)(row * AS_STRIDE + seg * 4) * 4;
            int sz = ok ? 16 : 0;
            asm volatile("cp.async.cg.shared.global [%0], [%1], 16, %2;"
                         :: "r"(daddr), "l"(p), "r"(sz));
        }
    };

    stage(0); asm volatile("cp.async.commit_group;");
    stage(1); asm volatile("cp.async.commit_group;");
    stage(2); asm volatile("cp.async.commit_group;");

    // stage W while loads fly
    for (int i4 = tid; i4 < K * 16; i4 += 256) {
        float4 w = __ldg((const float4*)W + i4);
        int flat = i4 * 4;
        uint32_t* d = &Ws[(flat >> 6) * WS_STRIDE + (flat & 63)];
        d[0] = f2tf32(w.x); d[1] = f2tf32(w.y); d[2] = f2tf32(w.z); d[3] = f2tf32(w.w);
    }

    float acc[2][8][4];
    #pragma unroll
    for (int mt = 0; mt < 2; mt++)
        #pragma unroll
        for (int nb = 0; nb < 8; nb++)
            #pragma unroll
            for (int c = 0; c < 4; c++) acc[mt][nb][c] = 0.f;

    #pragma unroll
    for (int c = 0; c < NC; c++) {
        if (c + 2 < NC)      asm volatile("cp.async.wait_group 2;");
        else if (c + 1 < NC) asm volatile("cp.async.wait_group 1;");
        else                 asm volatile("cp.async.wait_group 0;");
        __syncthreads();

        const uint32_t* A = As + (c % 3) * (256 * AS_STRIDE);
        #pragma unroll
        for (int ks = 0; ks < 2; ks++) {
            int kl = ks * 8;
            uint32_t a[2][4];
            #pragma unroll
            for (int mt = 0; mt < 2; mt++) {
                int rr = mrow + mt * 16;
                a[mt][0] = A[(rr + r)     * AS_STRIDE + kl + cq];
                a[mt][1] = A[(rr + r + 8) * AS_STRIDE + kl + cq];
                a[mt][2] = A[(rr + r)     * AS_STRIDE + kl + cq + 4];
                a[mt][3] = A[(rr + r + 8) * AS_STRIDE + kl + cq + 4];
            }
            #pragma unroll
            for (int nb = 0; nb < 8; nb++) {
                uint32_t b0 = Ws[(c * 16 + kl + cq)     * WS_STRIDE + nb * 8 + r];
                uint32_t b1 = Ws[(c * 16 + kl + cq + 4) * WS_STRIDE + nb * 8 + r];
                MMA_TF32(acc[0][nb], a[0], b0, b1);
                MMA_TF32(acc[1][nb], a[1], b0, b1);
            }
        }
        __syncthreads();
        if (c + 3 < NC) { stage(c + 3); asm volatile("cp.async.commit_group;"); }
    }

    #pragma unroll
    for (int mt = 0; mt < 2; mt++) {
        int row_a = row0 + mrow + mt * 16 + r;
        int row_b = row_a + 8;
        #pragma unroll
        for (int nb = 0; nb < 8; nb++) {
            int col = nb * 8 + cq * 2;
            if (row_a < n) {
                __nv_bfloat162 v = __float22bfloat162_rn(
                    make_float2(acc[mt][nb][0], acc[mt][nb][1]));
                *(__nv_bfloat162*)&out[(long)row_a * HH + col] = v;
            }
            if (row_b < n) {
                __nv_bfloat162 v = __float22bfloat162_rn(
                    make_float2(acc[mt][nb][2], acc[mt][nb][3]));
                *(__nv_bfloat162*)&out[(long)row_b * HH + col] = v;
            }
        }
    }
}

// ---------------------------------------------------------------------------
// GEMM2: bf16 X[n,64] @ W[64,64] -> bf16 out, scaled by dinv[row]. 256 threads.
__global__ __launch_bounds__(256) void gemm_bf16_kernel(
        const __nv_bfloat16* __restrict__ X, const float* __restrict__ W,
        const float* __restrict__ dinv, __nv_bfloat16* __restrict__ out, int n) {
    extern __shared__ uint32_t sm[];
    uint32_t* Ws = sm;                         // 64 * 72
    uint32_t* As = sm + 64 * WS_STRIDE;        // 128 * 68

    const int tid  = threadIdx.x;
    const int row0 = blockIdx.x * 128;
    const int warp = tid >> 5;
    const int lane = tid & 31;
    const int r    = lane >> 2;
    const int cq   = lane & 3;
    const int mrow = warp * 16;

    for (int i4 = tid; i4 < 64 * 16; i4 += 256) {
        float4 w = __ldg((const float4*)W + i4);
        int flat = i4 * 4;
        uint32_t* d = &Ws[(flat >> 6) * WS_STRIDE + (flat & 63)];
        d[0] = f2tf32(w.x); d[1] = f2tf32(w.y); d[2] = f2tf32(w.z); d[3] = f2tf32(w.w);
    }

    #pragma unroll
    for (int j = 0; j < 4; j++) {
        int i   = tid + j * 256;       // 0..1023
        int row = i >> 3, seg = i & 7;
        int grow = row0 + row;
        uint4 v = (grow < n) ? __ldg((const uint4*)(X + (long)grow * HH) + seg)
                             : make_uint4(0, 0, 0, 0);
        uint32_t* d = &As[row * AS2_STRIDE + seg * 8];
        d[0] = v.x << 16; d[1] = v.x & 0xFFFF0000u;
        d[2] = v.y << 16; d[3] = v.y & 0xFFFF0000u;
        d[4] = v.z << 16; d[5] = v.z & 0xFFFF0000u;
        d[6] = v.w << 16; d[7] = v.w & 0xFFFF0000u;
    }
    __syncthreads();

    float acc[8][4];
    #pragma unroll
    for (int nb = 0; nb < 8; nb++)
        #pragma unroll
        for (int c = 0; c < 4; c++) acc[nb][c] = 0.f;

    #pragma unroll
    for (int kg = 0; kg < 8; kg++) {
        int kl = kg * 8;
        uint32_t a[4];
        a[0] = As[(mrow + r)     * AS2_STRIDE + kl + cq];
        a[1] = As[(mrow + r + 8) * AS2_STRIDE + kl + cq];
        a[2] = As[(mrow + r)     * AS2_STRIDE + kl + cq + 4];
        a[3] = As[(mrow + r + 8) * AS2_STRIDE + kl + cq + 4];
        #pragma unroll
        for (int nb = 0; nb < 8; nb++) {
            uint32_t b0 = Ws[(kl + cq)     * WS_STRIDE + nb * 8 + r];
            uint32_t b1 = Ws[(kl + cq + 4) * WS_STRIDE + nb * 8 + r];
            MMA_TF32(acc[nb], a, b0, b1);
        }
    }

    int row_a = row0 + mrow + r;
    int row_b = row_a + 8;
    float sa = (row_a < n) ? dinv[row_a] : 0.f;
    float sb = (row_b < n) ? dinv[row_b] : 0.f;
    #pragma unroll
    for (int nb = 0; nb < 8; nb++) {
        int col = nb * 8 + cq * 2;
        if (row_a < n) {
            __nv_bfloat162 v = __float22bfloat162_rn(
                make_float2(acc[nb][0] * sa, acc[nb][1] * sa));
            *(__nv_bfloat162*)&out[(long)row_a * HH + col] = v;
        }
        if (row_b < n) {
            __nv_bfloat162 v = __float22bfloat162_rn(
                make_float2(acc[nb][2] * sb, acc[nb][3] * sb));
            *(__nv_bfloat162*)&out[(long)row_b * HH + col] = v;
        }
    }
}

// ---------------------------------------------------------------------------
// Gather with bf16x2 HADD2 accumulation (R12 form: 4-edge unroll).
// xs pre-scaled by dinv[src]. h[n] = relu(dinv[n] * Σ xs[s] + b).
// 8 threads/node, uint4 lanes.
template <bool POOL>
__global__ void gather_kernel(const int* __restrict__ deg, const int* __restrict__ bucket,
                              const __nv_bfloat16* __restrict__ xs,
                              const float* __restrict__ dinv,
                              const float* __restrict__ b,
                              __nv_bfloat16* __restrict__ out,
                              const int* __restrict__ batch,
                              float* __restrict__ pool, float* __restrict__ cntg,
                              int n) {
    int t = blockIdx.x * blockDim.x + threadIdx.x;
    int node = t >> 3;
    if (node >= n) return;
    int lane8 = t & 7;
    int c = lane8 << 3;

    int dcount = __ldg(&deg[node]);
    if (dcount > CAP) dcount = CAP;
    const int* lst = bucket + node * CAP;

    // self-loop message initializes the accumulator
    uint4 sv = __ldg((const uint4*)xs + (long)node * 8 + lane8);
    __nv_bfloat162 acc[4];
    {
        __nv_bfloat162* p = (__nv_bfloat162*)&sv;
        acc[0] = p[0]; acc[1] = p[1]; acc[2] = p[2]; acc[3] = p[3];
    }

    int e = 0;
    for (; e + 4 <= dcount; e += 4) {
        int4 s4 = __ldg((const int4*)(lst + e));
        uint4 v0 = __ldg((const uint4*)xs + (long)s4.x * 8 + lane8);
        uint4 v1 = __ldg((const uint4*)xs + (long)s4.y * 8 + lane8);
        uint4 v2 = __ldg((const uint4*)xs + (long)s4.z * 8 + lane8);
        uint4 v3 = __ldg((const uint4*)xs + (long)s4.w * 8 + lane8);
        __nv_bfloat162* p0 = (__nv_bfloat162*)&v0;
        __nv_bfloat162* p1 = (__nv_bfloat162*)&v1;
        __nv_bfloat162* p2 = (__nv_bfloat162*)&v2;
        __nv_bfloat162* p3 = (__nv_bfloat162*)&v3;
        #pragma unroll
        for (int k = 0; k < 4; k++) {
            acc[k] = __hadd2(acc[k], __hadd2(__hadd2(p0[k], p1[k]),
                                             __hadd2(p2[k], p3[k])));
        }
    }
    for (; e < dcount; e++) {
        int s = __ldg(&lst[e]);
        uint4 v = __ldg((const uint4*)xs + (long)s * 8 + lane8);
        __nv_bfloat162* p = (__nv_bfloat162*)&v;
        #pragma unroll
        for (int k = 0; k < 4; k++) acc[k] = __hadd2(acc[k], p[k]);
    }

    float sc = __ldg(&dinv[node]);
    float o[8];
    #pragma unroll
    for (int k = 0; k < 4; k++) {
        float2 f = __bfloat1622float2(acc[k]);
        o[k * 2 + 0] = fmaxf(fmaf(sc, f.x, __ldg(&b[c + k * 2 + 0])), 0.f);
        o[k * 2 + 1] = fmaxf(fmaf(sc, f.y, __ldg(&b[c + k * 2 + 1])), 0.f);
    }

    if (!POOL) {
        uint4 pk;
        __nv_bfloat162 h0 = __float22bfloat162_rn(make_float2(o[0], o[1]));
        __nv_bfloat162 h1 = __float22bfloat162_rn(make_float2(o[2], o[3]));
        __nv_bfloat162 h2 = __float22bfloat162_rn(make_float2(o[4], o[5]));
        __nv_bfloat162 h3 = __float22bfloat162_rn(make_float2(o[6], o[7]));
        pk.x = *(uint32_t*)&h0; pk.y = *(uint32_t*)&h1;
        pk.z = *(uint32_t*)&h2; pk.w = *(uint32_t*)&h3;
        *((uint4*)out + (long)node * 8 + lane8) = pk;
    } else {
        int g = __ldg(&batch[node]);
        float* p = pool + g * HH + c;
        asm volatile("red.global.add.v4.f32 [%0], {%1,%2,%3,%4};"
                     :: "l"(p), "f"(o[0]), "f"(o[1]), "f"(o[2]), "f"(o[3]) : "memory");
        asm volatile("red.global.add.v4.f32 [%0], {%1,%2,%3,%4};"
                     :: "l"(p + 4), "f"(o[4]), "f"(o[5]), "f"(o[6]), "f"(o[7]) : "memory");
        if (lane8 == 0) atomicAdd(&cntg[g], 1.0f);
    }
}

// ---------------------------------------------------------------------------
__global__ void head_kernel(const float* __restrict__ pool, const float* __restrict__ cnt,
                            const float* __restrict__ Wl, const float* __restrict__ bl,
                            float* __restrict__ out) {
    int g = blockIdx.x * blockDim.x + threadIdx.x;
    if (g >= GG) return;
    float inv = 1.0f / fmaxf(cnt[g], 1.0f);
    float acc = 0.f;
    #pragma unroll
    for (int k = 0; k < HH; k++) acc += pool[g * HH + k] * __ldg(&Wl[k]);
    float z = acc * inv + __ldg(&bl[0]);
    out[g] = 1.0f / (1.0f + expf(-z));
}

// ---------------------------------------------------------------------------
extern "C" void kernel_launch(void* const* d_in, const int* in_sizes, int n_in,
                              void* d_out, int out_size) {
    const float* x     = (const float*)d_in[0];
    const int*   ei    = (const int*)  d_in[1];
    const int*   batch = (const int*)  d_in[2];
    const float* W1    = (const float*)d_in[3];
    const float* b1    = (const float*)d_in[4];
    const float* W2    = (const float*)d_in[5];
    const float* b2    = (const float*)d_in[6];
    const float* Wl    = (const float*)d_in[7];
    const float* bl    = (const float*)d_in[8];

    const int n = in_sizes[0] / FIN;
    const int E = in_sizes[1] / 2;
    const int* src = ei;
    const int* dst = ei + E;

    float *dinv, *pool, *cnt;
    __nv_bfloat16 *XS, *H1;
    int *deg, *bucket;
    cudaGetSymbolAddress((void**)&dinv,   g_dinv);
    cudaGetSymbolAddress((void**)&XS,     g_xs);
    cudaGetSymbolAddress((void**)&H1,     g_h1);
    cudaGetSymbolAddress((void**)&pool,   g_pool);
    cudaGetSymbolAddress((void**)&cnt,    g_cnt);
    cudaGetSymbolAddress((void**)&deg,    g_deg);
    cudaGetSymbolAddress((void**)&bucket, g_bucket);

    const int SMEM1 = (FIN * WS_STRIDE + 3 * 256 * AS_STRIDE) * 4;  // 98304
    const int SMEM2 = (HH * WS_STRIDE + 128 * AS2_STRIDE) * 4;      // 53248
    cudaFuncSetAttribute(gemm_f32_kernel,
                         cudaFuncAttributeMaxDynamicSharedMemorySize, SMEM1);
    cudaFuncSetAttribute(gemm_bf16_kernel,
                         cudaFuncAttributeMaxDynamicSharedMemorySize, SMEM2);

    const int GB1 = (n + 255) / 256;
    const int GB2 = (n + 127) / 128;

    // main stream: init (deg/pool/cnt)
    init_kernel<<<(n + 255) / 256, 256>>>(deg, pool, cnt, n);

    // fork: side stream builds adjacency + dinv, main stream runs GEMM1
    cudaEventRecord(g_ev_fork, 0);
    cudaStreamWaitEvent(g_s1, g_ev_fork, 0);

    fill_kernel<<<(E / 4 + 255) / 256, 256, 0, g_s1>>>(src, dst, deg, bucket, E);
    dinv_kernel<<<(n + 255) / 256, 256, 0, g_s1>>>(deg, dinv, n);
    cudaEventRecord(g_ev_join, g_s1);

    gemm_f32_kernel<<<GB1, 256, SMEM1>>>(x, W1, XS, n);   // unscaled xs

    // join, then apply dinv scaling to xs (f32 math)
    cudaStreamWaitEvent(0, g_ev_join, 0);
    scale_kernel<<<(n * 8 + 255) / 256, 256>>>(XS, dinv, n);

    // layer 1 aggregate (pure HADD2)
    gather_kernel<false><<<(n * 8 + 255) / 256, 256>>>(
        deg, bucket, XS, dinv, b1, H1, nullptr, nullptr, nullptr, n);

    // layer 2: xs2 = dinv*(h1@W2); aggregate fused with relu + mean-pool
    gemm_bf16_kernel<<<GB2, 256, SMEM2>>>(H1, W2, dinv, XS, n);
    gather_kernel<true><<<(n * 8 + 255) / 256, 256>>>(
        deg, bucket, XS, dinv, b2, nullptr, batch, pool, cnt, n);

    head_kernel<<<(GG + 255) / 256, 256>>>(pool, cnt, Wl, bl, (float*)d_out);
}